// round 13
// baseline (speedup 1.0000x reference)
#include <cuda_runtime.h>
#include <cuda_bf16.h>
#include <math.h>
#include <stdint.h>

#define BATCH 2
#define SEQ   2048
#define DIM   2048
#define NH    16
#define NKV   8
#define HD    128
#define KVD   (NKV*HD)
#define SK    64
#define INV_SQRT_HD 0.08838834764831845f  /* 1/sqrt(128) */

/* ------------------------- scratch (static device) ------------------------ */
/* split-pair (bf16 hi/lo interleaved) intermediates, 64 words per row */
__device__ uint32_t g_ASB [(size_t)3*BATCH*SEQ*SK];
__device__ uint32_t g_ASoB[(size_t)BATCH*SEQ*SK];
__device__ uint32_t g_TqB [(size_t)BATCH*DIM*SK];
__device__ uint32_t g_TkB [(size_t)BATCH*KVD*SK];
__device__ uint32_t g_TvB [(size_t)BATCH*KVD*SK];
__device__ uint32_t g_ToB [(size_t)BATCH*DIM*SK];
/* fp32 tensors */
__device__ float g_q  [(size_t)BATCH*NH *SEQ*HD];
__device__ float g_k  [(size_t)BATCH*NKV*SEQ*HD];
__device__ float g_vT [(size_t)BATCH*NKV*HD*SEQ];   /* [b,kvh][d][s] */
__device__ float g_ao [(size_t)BATCH*SEQ*DIM];
/* pre-split sketch matrices, MMA-B layout: [which][b][n=64][k word] */
__device__ uint32_t g_SB [(size_t)4*BATCH*64*2048];

/* ---------------------- bf16 split / mma helpers ---------------------- */
__device__ __forceinline__ uint32_t pack_bf16(float a, float b) {
    __nv_bfloat162 t = __floats2bfloat162_rn(a, b);
    return *reinterpret_cast<uint32_t*>(&t);
}
__device__ __forceinline__ void split2(float a, float b,
                                       uint32_t& hi, uint32_t& lo) {
    float ha = __bfloat162float(__float2bfloat16_rn(a));
    float hb = __bfloat162float(__float2bfloat16_rn(b));
    hi = pack_bf16(ha, hb);
    lo = pack_bf16(a - ha, b - hb);
}
__device__ __forceinline__ void mma_bf16(float* c, const uint32_t* a,
                                         uint32_t b0, uint32_t b1) {
    asm volatile(
        "mma.sync.aligned.m16n8k16.row.col.f32.bf16.bf16.f32 "
        "{%0,%1,%2,%3}, {%4,%5,%6,%7}, {%8,%9}, {%0,%1,%2,%3};"
        : "+f"(c[0]), "+f"(c[1]), "+f"(c[2]), "+f"(c[3])
        : "r"(a[0]), "r"(a[1]), "r"(a[2]), "r"(a[3]), "r"(b0), "r"(b1));
}
__device__ __forceinline__ void mma3b(float* c,
                                      const uint32_t* ah, const uint32_t* al,
                                      uint32_t bh0, uint32_t bh1,
                                      uint32_t bl0, uint32_t bl1) {
    mma_bf16(c, al, bh0, bh1);
    mma_bf16(c, ah, bl0, bl1);
    mma_bf16(c, ah, bh0, bh1);
}

/* =====================================================================
 * k_splitS: pre-split all four sketch matrices into MMA-B layout.
 * =====================================================================*/
__global__ void k_splitS(const float* __restrict__ Sq, const float* __restrict__ Sk,
                         const float* __restrict__ Sv, const float* __restrict__ So)
{
    int t = blockIdx.x*256 + threadIdx.x;
    int jq = t & 1023;
    int n  = (t >> 10) & 63;
    int b  = (t >> 16) & 1;
    int which = t >> 17;
    const float* S = (which==0?Sq:which==1?Sk:which==2?Sv:So) + (size_t)b*DIM*SK;
    float f0 = S[(size_t)(2*jq  )*SK + n];
    float f1 = S[(size_t)(2*jq+1)*SK + n];
    uint32_t hi, lo;
    split2(f0, f1, hi, lo);
    *(uint2*)(g_SB + (((size_t)which*BATCH + b)*64 + n)*2048 + (size_t)jq*2) =
        make_uint2(hi, lo);
}

/* =====================================================================
 * k_gemm_mma: multi-job GEMM, C = alpha * A(Mx2048) @ B^T (N=64).
 *   Double-buffered, register-prefetched (round 12). Epilogue now
 *   writes C in split-pair layout ([row][32 pairs][hi,lo] words).
 * =====================================================================*/
#define GAS 40
#define GBUF ((128 + 64) * GAS)
#define GEMM_SMEM (2 * GBUF * 4)

struct GemmJobs {
    const float*    A[7];
    const uint32_t* B[7];
    uint32_t*       C[7];
    long  sAb[7];
    long  sBb[7];
    long  sCb[7];   /* words */
    int   mtiles[7];
    float alpha[7];
};

__global__ void __launch_bounds__(256, 1) k_gemm_mma(GemmJobs J)
{
    extern __shared__ uint32_t smg[];
    int job = blockIdx.y, b = blockIdx.z;
    if ((int)blockIdx.x >= J.mtiles[job]) return;
    int tm0 = blockIdx.x * 128;
    const float*    A = J.A[job] + (size_t)b*J.sAb[job] + (size_t)tm0*DIM;
    const uint32_t* B = J.B[job] + (size_t)b*J.sBb[job];
    uint32_t*       C = J.C[job] + (size_t)b*J.sCb[job] + (size_t)tm0*SK;
    float alpha = J.alpha[job];

    int tid = threadIdx.x, lane = tid & 31, w = tid >> 5;
    int gid = lane >> 2, qd = lane & 3;
    int m0 = w*16;
    int ar = tid >> 1, ahalf = tid & 1;
    int bn = tid >> 3, bj4 = tid & 7;

    float acc[8][4] = {};
    float4 av[4];
    uint4  bv[2];

    {
        const float* Ap = A + (size_t)ar*DIM + ahalf*16;
        av[0] = ((const float4*)Ap)[0]; av[1] = ((const float4*)Ap)[1];
        av[2] = ((const float4*)Ap)[2]; av[3] = ((const float4*)Ap)[3];
        bv[0] = *(const uint4*)(B + (size_t)bn*2048 + bj4*4);
        bv[1] = *(const uint4*)(B + (size_t)(bn+32)*2048 + bj4*4);
    }
    {
        uint32_t* dA = smg;
        uint32_t* dB = smg + 128*GAS;
        #pragma unroll
        for (int i = 0; i < 4; i++) {
            uint32_t h01, l01, h23, l23;
            split2(av[i].x, av[i].y, h01, l01);
            split2(av[i].z, av[i].w, h23, l23);
            *(uint4*)(dA + (size_t)ar*GAS + ahalf*16 + i*4) =
                make_uint4(h01, l01, h23, l23);
        }
        *(uint4*)(dB + (size_t)bn*GAS + bj4*4)      = bv[0];
        *(uint4*)(dB + (size_t)(bn+32)*GAS + bj4*4) = bv[1];
    }
    __syncthreads();

    for (int it = 0; it < 64; it++) {
        uint32_t* sA = smg + (it & 1)*GBUF;
        uint32_t* sB = sA + 128*GAS;
        bool more = (it + 1 < 64);
        if (more) {
            int k0 = (it + 1)*32;
            const float* Ap = A + (size_t)ar*DIM + k0 + ahalf*16;
            av[0] = ((const float4*)Ap)[0]; av[1] = ((const float4*)Ap)[1];
            av[2] = ((const float4*)Ap)[2]; av[3] = ((const float4*)Ap)[3];
            bv[0] = *(const uint4*)(B + (size_t)bn*2048 + k0 + bj4*4);
            bv[1] = *(const uint4*)(B + (size_t)(bn+32)*2048 + k0 + bj4*4);
        }
        #pragma unroll
        for (int ks = 0; ks < 2; ks++) {
            uint2 qa0 = *(const uint2*)(sA + (size_t)(m0+gid  )*GAS + (8*ks+qd  )*2);
            uint2 qa1 = *(const uint2*)(sA + (size_t)(m0+gid+8)*GAS + (8*ks+qd  )*2);
            uint2 qa2 = *(const uint2*)(sA + (size_t)(m0+gid  )*GAS + (8*ks+qd+4)*2);
            uint2 qa3 = *(const uint2*)(sA + (size_t)(m0+gid+8)*GAS + (8*ks+qd+4)*2);
            uint32_t ah[4] = {qa0.x, qa1.x, qa2.x, qa3.x};
            uint32_t al[4] = {qa0.y, qa1.y, qa2.y, qa3.y};
            #pragma unroll
            for (int nt = 0; nt < 8; nt++) {
                uint2 kb0 = *(const uint2*)(sB + (size_t)(nt*8+gid)*GAS + (8*ks+qd  )*2);
                uint2 kb1 = *(const uint2*)(sB + (size_t)(nt*8+gid)*GAS + (8*ks+qd+4)*2);
                mma3b(acc[nt], ah, al, kb0.x, kb1.x, kb0.y, kb1.y);
            }
        }
        if (more) {
            uint32_t* dA = smg + ((it + 1) & 1)*GBUF;
            uint32_t* dB = dA + 128*GAS;
            #pragma unroll
            for (int i = 0; i < 4; i++) {
                uint32_t h01, l01, h23, l23;
                split2(av[i].x, av[i].y, h01, l01);
                split2(av[i].z, av[i].w, h23, l23);
                *(uint4*)(dA + (size_t)ar*GAS + ahalf*16 + i*4) =
                    make_uint4(h01, l01, h23, l23);
            }
            *(uint4*)(dB + (size_t)bn*GAS + bj4*4)      = bv[0];
            *(uint4*)(dB + (size_t)(bn+32)*GAS + bj4*4) = bv[1];
            __syncthreads();
        }
    }

    /* ---- epilogue: write split-pair layout ---- */
    #pragma unroll
    for (int nt = 0; nt < 8; nt++) {
        uint2 u0, u1;
        split2(acc[nt][0]*alpha, acc[nt][1]*alpha, u0.x, u0.y);
        split2(acc[nt][2]*alpha, acc[nt][3]*alpha, u1.x, u1.y);
        *(uint2*)(C + (size_t)(m0+gid  )*SK + (nt*4+qd)*2) = u0;
        *(uint2*)(C + (size_t)(m0+gid+8)*SK + (nt*4+qd)*2) = u1;
    }
}

/* =====================================================================
 * k_proj_mma: X = ASs @ Ts^T via 3-MMA bf16 split, K=64 (4 k-steps).
 *   128x64 tile, 8 warps. Inputs pre-split. Epilogues:
 *     mode 0/1: RoPE -> g_q/g_k [b,h][s][d]
 *     mode 2:   smem transpose -> g_vT [b,kvh][d][s]
 *     mode 3:   d_out [b][s][m]
 *   phase 0: grid (16, 64, B): y<32 mode0, y<48 mode1, else mode2.
 *   phase 1: grid (16, 32, B): mode3.
 * =====================================================================*/
#define PJS 72
#define PROJ_SMEM ((128*PJS + 64*PJS) * 4)   /* 55296 B */

__global__ void __launch_bounds__(256, 1) k_proj_mma(
    const float* __restrict__ freqs, float* __restrict__ dout, int phase)
{
    extern __shared__ uint32_t smp[];
    uint32_t* sA = smp;              /* [128][72] */
    uint32_t* sB = smp + 128*PJS;    /* [64][72]  */

    int b = blockIdx.z, y = blockIdx.y;
    int mode, mt;
    if (phase)       { mode = 3; mt = y; }
    else if (y < 32) { mode = 0; mt = y; }
    else if (y < 48) { mode = 1; mt = y - 32; }
    else             { mode = 2; mt = y - 48; }
    int s0 = blockIdx.x * 128, m0g = mt * 64;

    const uint32_t* Asrc;
    const uint32_t* Bsrc;
    if      (mode == 0) { Asrc = g_ASB + ((size_t)0*BATCH + b)*SEQ*SK; Bsrc = g_TqB + (size_t)b*DIM*SK; }
    else if (mode == 1) { Asrc = g_ASB + ((size_t)1*BATCH + b)*SEQ*SK; Bsrc = g_TkB + (size_t)b*KVD*SK; }
    else if (mode == 2) { Asrc = g_ASB + ((size_t)2*BATCH + b)*SEQ*SK; Bsrc = g_TvB + (size_t)b*KVD*SK; }
    else                { Asrc = g_ASoB + (size_t)b*SEQ*SK;            Bsrc = g_ToB + (size_t)b*DIM*SK; }

    int tid = threadIdx.x, lane = tid & 31, w = tid >> 5;
    int gid = lane >> 2, qd = lane & 3;
    int m0 = w*16;

    #pragma unroll
    for (int it = 0; it < 8; it++) {
        int idx = tid + it*256;
        int r = idx >> 4, c4 = (idx & 15)*4;
        *(uint4*)(sA + (size_t)r*PJS + c4) =
            *(const uint4*)(Asrc + (size_t)(s0 + r)*SK + c4);
    }
    #pragma unroll
    for (int it = 0; it < 4; it++) {
        int idx = tid + it*256;
        int r = idx >> 4, c4 = (idx & 15)*4;
        *(uint4*)(sB + (size_t)r*PJS + c4) =
            *(const uint4*)(Bsrc + (size_t)(m0g + r)*SK + c4);
    }
    __syncthreads();

    float acc[8][4] = {};
    #pragma unroll
    for (int ks = 0; ks < 4; ks++) {
        uint2 qa0 = *(const uint2*)(sA + (size_t)(m0+gid  )*PJS + (8*ks+qd  )*2);
        uint2 qa1 = *(const uint2*)(sA + (size_t)(m0+gid+8)*PJS + (8*ks+qd  )*2);
        uint2 qa2 = *(const uint2*)(sA + (size_t)(m0+gid  )*PJS + (8*ks+qd+4)*2);
        uint2 qa3 = *(const uint2*)(sA + (size_t)(m0+gid+8)*PJS + (8*ks+qd+4)*2);
        uint32_t ah[4] = {qa0.x, qa1.x, qa2.x, qa3.x};
        uint32_t al[4] = {qa0.y, qa1.y, qa2.y, qa3.y};
        #pragma unroll
        for (int nt = 0; nt < 8; nt++) {
            uint2 kb0 = *(const uint2*)(sB + (size_t)(nt*8+gid)*PJS + (8*ks+qd  )*2);
            uint2 kb1 = *(const uint2*)(sB + (size_t)(nt*8+gid)*PJS + (8*ks+qd+4)*2);
            mma3b(acc[nt], ah, al, kb0.x, kb1.x, kb0.y, kb1.y);
        }
    }

    if (mode == 3) {
        #pragma unroll
        for (int nt = 0; nt < 8; nt++) {
            int c = nt*8 + 2*qd;
            *(float2*)(dout + ((size_t)b*SEQ + s0+m0+gid  )*DIM + m0g + c) =
                make_float2(acc[nt][0], acc[nt][1]);
            *(float2*)(dout + ((size_t)b*SEQ + s0+m0+gid+8)*DIM + m0g + c) =
                make_float2(acc[nt][2], acc[nt][3]);
        }
    } else if (mode == 2) {
        /* transpose in smem (aliases sA), then coalesced write to g_vT */
        __syncthreads();
        float* st = (float*)smp;   /* [64][132] */
        #pragma unroll
        for (int nt = 0; nt < 8; nt++) {
            int c = nt*8 + 2*qd;
            st[(size_t)(c  )*132 + m0+gid  ] = acc[nt][0];
            st[(size_t)(c+1)*132 + m0+gid  ] = acc[nt][1];
            st[(size_t)(c  )*132 + m0+gid+8] = acc[nt][2];
            st[(size_t)(c+1)*132 + m0+gid+8] = acc[nt][3];
        }
        __syncthreads();
        int h = m0g >> 7, d0b = m0g & 127;
        float* Vt = g_vT + ((size_t)(b*NKV + h)*HD + d0b)*SEQ;
        #pragma unroll
        for (int it = 0; it < 8; it++) {
            int slot = tid + it*256;
            int d = slot >> 5, s4 = (slot & 31)*4;
            float4 v = *(float4*)(st + (size_t)d*132 + s4);
            *(float4*)(Vt + (size_t)d*SEQ + s0 + s4) = v;
        }
    } else {
        int h = m0g >> 7;
        float* base = (mode == 0) ? g_q + ((size_t)(b*NH  + h))*SEQ*HD
                                  : g_k + ((size_t)(b*NKV + h))*SEQ*HD;
        #pragma unroll
        for (int nt = 0; nt < 8; nt++) {
            int c  = nt*8 + 2*qd;
            int d0 = (m0g & 127) + c;
            int dh = d0 >> 1;
            int srA = s0 + m0 + gid, srB = srA + 8;
            const float* fA = freqs + ((size_t)srA*64 + dh)*2;
            float c0 = fA[0], n0 = fA[1];
            *(float2*)(base + (size_t)srA*HD + d0) =
                make_float2(acc[nt][0]*n0 - acc[nt][1]*c0,
                            acc[nt][0]*c0 + acc[nt][1]*n0);
            const float* fB = freqs + ((size_t)srB*64 + dh)*2;
            float c1 = fB[0], n1 = fB[1];
            *(float2*)(base + (size_t)srB*HD + d0) =
                make_float2(acc[nt][2]*n1 - acc[nt][3]*c1,
                            acc[nt][2]*c1 + acc[nt][3]*n1);
        }
    }
}

/* =====================================================================
 * k_flash: causal flash attention, 2-term bf16 split, mma m16n8k16.
 *   BM=128, BN=128 (new). V read pre-transposed from g_vT (no staging).
 *   smem: sQ[128][136], sK/sP[128][136] (aliased), sV[128][136].
 *   grid (SEQ/128, NH, B); GQA kv head = h>>1; tail-first scheduling.
 * =====================================================================*/
#define FS 136
#define FSQ_OFF 0
#define FSK_OFF (128*FS)
#define FSV_OFF (2*128*FS)
#define FLASH_SMEM (3*128*FS*4)   /* 208896 B */

__global__ void __launch_bounds__(256, 1) k_flash()
{
    extern __shared__ uint32_t smw[];
    uint32_t* sQ = smw + FSQ_OFF;
    uint32_t* sK = smw + FSK_OFF;
    uint32_t* sP = sK;                  /* aliased: P written after QK */
    uint32_t* sV = smw + FSV_OFF;

    int tid = threadIdx.x, lane = tid & 31, w = tid >> 5;
    int qt = (int)gridDim.x - 1 - (int)blockIdx.x;
    int h = blockIdx.y, b = blockIdx.z;
    int gid = lane >> 2, qd = lane & 3;

    const float* Qg = g_q  + ((size_t)(b*NH  + h))     *SEQ*HD + (size_t)qt*128*HD;
    const float* Kb = g_k  + ((size_t)(b*NKV + (h>>1)))*SEQ*HD;
    const float* Vt = g_vT + ((size_t)(b*NKV + (h>>1)))*HD*SEQ;

    /* ---- load Q tile: scale, split ---- */
    #pragma unroll
    for (int it = 0; it < 16; it++) {
        int slot = tid + it*256;
        int r = slot >> 5, c4 = (slot & 31) * 4;
        float4 v = *(const float4*)(Qg + (size_t)r*HD + c4);
        uint32_t h01, l01, h23, l23;
        split2(v.x*INV_SQRT_HD, v.y*INV_SQRT_HD, h01, l01);
        split2(v.z*INV_SQRT_HD, v.w*INV_SQRT_HD, h23, l23);
        *(uint4*)(sQ + (size_t)r*FS + c4) = make_uint4(h01, l01, h23, l23);
    }

    int m0 = w*16;
    float o[16][4] = {};
    float miA = -1e30f, miB = -1e30f, liA = 0.f, liB = 0.f;
    int row_min = qt*128 + w*16;
    int nkt = qt + 1;

    for (int kt = 0; kt < nkt; kt++) {
        const float* Kg = Kb + (size_t)kt*128*HD;
        /* ---- K: load + split (128 rows x 128 d) ---- */
        #pragma unroll
        for (int it = 0; it < 16; it++) {
            int slot = tid + it*256;
            int r = slot >> 5, c4 = (slot & 31) * 4;
            float4 kv = *(const float4*)(Kg + (size_t)r*HD + c4);
            uint32_t h01, l01, h23, l23;
            split2(kv.x, kv.y, h01, l01);
            split2(kv.z, kv.w, h23, l23);
            *(uint4*)(sK + (size_t)r*FS + c4) = make_uint4(h01, l01, h23, l23);
        }
        /* ---- V: load pre-transposed [d][p], split into pairs ---- */
        #pragma unroll
        for (int it = 0; it < 16; it++) {
            int slot = tid + it*256;
            int d = slot >> 5, p4 = (slot & 31) * 4;
            float4 vv = *(const float4*)(Vt + (size_t)d*SEQ + kt*128 + p4);
            uint32_t h01, l01, h23, l23;
            split2(vv.x, vv.y, h01, l01);
            split2(vv.z, vv.w, h23, l23);
            *(uint4*)(sV + (size_t)d*FS + p4) = make_uint4(h01, l01, h23, l23);
        }
        __syncthreads();

        /* ---- S = Q K^T (128x128 per CTA; 16 rows x 128 cols per warp) ---- */
        float s[16][4] = {};
        #pragma unroll
        for (int ks = 0; ks < 8; ks++) {
            uint2 qa0 = *(const uint2*)(sQ + (size_t)(m0+gid  )*FS + (8*ks+qd  )*2);
            uint2 qa1 = *(const uint2*)(sQ + (size_t)(m0+gid+8)*FS + (8*ks+qd  )*2);
            uint2 qa2 = *(const uint2*)(sQ + (size_t)(m0+gid  )*FS + (8*ks+qd+4)*2);
            uint2 qa3 = *(const uint2*)(sQ + (size_t)(m0+gid+8)*FS + (8*ks+qd+4)*2);
            uint32_t ah[4] = {qa0.x, qa1.x, qa2.x, qa3.x};
            uint32_t al[4] = {qa0.y, qa1.y, qa2.y, qa3.y};
            #pragma unroll
            for (int nt = 0; nt < 16; nt++) {
                uint2 kb0 = *(const uint2*)(sK + (size_t)(nt*8+gid)*FS + (8*ks+qd  )*2);
                uint2 kb1 = *(const uint2*)(sK + (size_t)(nt*8+gid)*FS + (8*ks+qd+4)*2);
                mma3b(s[nt], ah, al, kb0.x, kb1.x, kb0.y, kb1.y);
            }
        }

        /* ---- causal mask (diagonal tile only) ---- */
        if (kt == qt) {
            int rA = row_min + gid, rB = rA + 8;
            #pragma unroll
            for (int nt = 0; nt < 16; nt++) {
                int c0 = kt*128 + nt*8 + 2*qd;
                if (c0     > rA) s[nt][0] = -1e30f;
                if (c0 + 1 > rA) s[nt][1] = -1e30f;
                if (c0     > rB) s[nt][2] = -1e30f;
                if (c0 + 1 > rB) s[nt][3] = -1e30f;
            }
        }

        /* ---- online softmax (rows A=gid, B=gid+8; 4-lane groups) ---- */
        float mA = -1e30f, mB = -1e30f;
        #pragma unroll
        for (int nt = 0; nt < 16; nt++) {
            mA = fmaxf(mA, fmaxf(s[nt][0], s[nt][1]));
            mB = fmaxf(mB, fmaxf(s[nt][2], s[nt][3]));
        }
        mA = fmaxf(mA, __shfl_xor_sync(0xffffffffu, mA, 1));
        mA = fmaxf(mA, __shfl_xor_sync(0xffffffffu, mA, 2));
        mB = fmaxf(mB, __shfl_xor_sync(0xffffffffu, mB, 1));
        mB = fmaxf(mB, __shfl_xor_sync(0xffffffffu, mB, 2));
        float newmA = fmaxf(miA, mA), newmB = fmaxf(miB, mB);
        float alA = __expf(miA - newmA), alB = __expf(miB - newmB);
        float sumA = 0.f, sumB = 0.f;
        #pragma unroll
        for (int nt = 0; nt < 16; nt++) {
            s[nt][0] = __expf(s[nt][0] - newmA);
            s[nt][1] = __expf(s[nt][1] - newmA);
            s[nt][2] = __expf(s[nt][2] - newmB);
            s[nt][3] = __expf(s[nt][3] - newmB);
            sumA += s[nt][0] + s[nt][1];
            sumB += s[nt][2] + s[nt][3];
        }
        sumA += __shfl_xor_sync(0xffffffffu, sumA, 1);
        sumA += __shfl_xor_sync(0xffffffffu, sumA, 2);
        sumB += __shfl_xor_sync(0xffffffffu, sumB, 1);
        sumB += __shfl_xor_sync(0xffffffffu, sumB, 2);
        liA = liA*alA + sumA;  miA = newmA;
        liB = liB*alB + sumB;  miB = newmB;

        /* ---- rescale O ---- */
        #pragma unroll
        for (int nt = 0; nt < 16; nt++) {
            o[nt][0] *= alA; o[nt][1] *= alA;
            o[nt][2] *= alB; o[nt][3] *= alB;
        }

        /* K reads done before P (aliased) is written */
        __syncthreads();

        /* ---- store P split (own warp's rows only) ---- */
        #pragma unroll
        for (int nt = 0; nt < 16; nt++) {
            uint32_t hA, lA, hB, lB;
            split2(s[nt][0], s[nt][1], hA, lA);
            split2(s[nt][2], s[nt][3], hB, lB);
            *(uint2*)(sP + (size_t)(m0+gid  )*FS + (nt*4+qd)*2) = make_uint2(hA, lA);
            *(uint2*)(sP + (size_t)(m0+gid+8)*FS + (nt*4+qd)*2) = make_uint2(hB, lB);
        }
        __syncwarp();

        /* ---- O += P V ---- */
        #pragma unroll
        for (int ks = 0; ks < 8; ks++) {
            uint2 pa0 = *(const uint2*)(sP + (size_t)(m0+gid  )*FS + (8*ks+qd  )*2);
            uint2 pa1 = *(const uint2*)(sP + (size_t)(m0+gid+8)*FS + (8*ks+qd  )*2);
            uint2 pa2 = *(const uint2*)(sP + (size_t)(m0+gid  )*FS + (8*ks+qd+4)*2);
            uint2 pa3 = *(const uint2*)(sP + (size_t)(m0+gid+8)*FS + (8*ks+qd+4)*2);
            uint32_t ph[4] = {pa0.x, pa1.x, pa2.x, pa3.x};
            uint32_t pl[4] = {pa0.y, pa1.y, pa2.y, pa3.y};
            #pragma unroll
            for (int nt = 0; nt < 16; nt++) {
                uint2 vb0 = *(const uint2*)(sV + (size_t)(nt*8+gid)*FS + (8*ks+qd  )*2);
                uint2 vb1 = *(const uint2*)(sV + (size_t)(nt*8+gid)*FS + (8*ks+qd+4)*2);
                mma3b(o[nt], ph, pl, vb0.x, vb1.x, vb0.y, vb1.y);
            }
        }
        __syncthreads();
    }

    /* ---- epilogue: O/l -> g_ao [b, s, h*HD + d] ---- */
    float invA = 1.0f / liA, invB = 1.0f / liB;
    float* Og = g_ao + ((size_t)b*SEQ + (size_t)qt*128)*DIM + (size_t)h*HD;
    #pragma unroll
    for (int nt = 0; nt < 16; nt++) {
        int c = nt*8 + 2*qd;
        float2 vA = make_float2(o[nt][0]*invA, o[nt][1]*invA);
        float2 vB = make_float2(o[nt][2]*invB, o[nt][3]*invB);
        *(float2*)(Og + (size_t)(m0 + gid)    *HD*NH + c) = vA;   /* DIM == HD*NH */
        *(float2*)(Og + (size_t)(m0 + gid + 8)*HD*NH + c) = vB;
    }
}

/* ========================= launch ========================= */
extern "C" void kernel_launch(void* const* d_in, const int* in_sizes, int n_in,
                              void* d_out, int out_size)
{
    const float* x  = (const float*)d_in[0];
    const float* wq = (const float*)d_in[1];
    const float* wk = (const float*)d_in[2];
    const float* wv = (const float*)d_in[3];
    const float* wo = (const float*)d_in[4];
    const float* Sq = (const float*)d_in[5];
    const float* Sk = (const float*)d_in[6];
    const float* Sv = (const float*)d_in[7];
    const float* So = (const float*)d_in[8];
    const float* fr = (const float*)d_in[9];
    float* out = (float*)d_out;

    cudaFuncSetAttribute(k_flash, cudaFuncAttributeMaxDynamicSharedMemorySize,
                         FLASH_SMEM);
    cudaFuncSetAttribute(k_gemm_mma, cudaFuncAttributeMaxDynamicSharedMemorySize,
                         GEMM_SMEM);
    cudaFuncSetAttribute(k_proj_mma, cudaFuncAttributeMaxDynamicSharedMemorySize,
                         PROJ_SMEM);

    uint32_t* dSB;   cudaGetSymbolAddress((void**)&dSB,   g_SB);
    uint32_t* dASB;  cudaGetSymbolAddress((void**)&dASB,  g_ASB);
    uint32_t* dASoB; cudaGetSymbolAddress((void**)&dASoB, g_ASoB);
    uint32_t* dTqB;  cudaGetSymbolAddress((void**)&dTqB,  g_TqB);
    uint32_t* dTkB;  cudaGetSymbolAddress((void**)&dTkB,  g_TkB);
    uint32_t* dTvB;  cudaGetSymbolAddress((void**)&dTvB,  g_TvB);
    uint32_t* dToB;  cudaGetSymbolAddress((void**)&dToB,  g_ToB);
    float*    dAo;   cudaGetSymbolAddress((void**)&dAo,   g_ao);

    dim3 blk(256);
    const long SBw  = 64L*2048;
    const long SBwb = (long)BATCH*SBw;

    /* pre-split sketches into MMA-B layout */
    k_splitS<<<2048, blk>>>(Sq, Sk, Sv, So);

    /* all 7 pre-attention GEMMs in ONE launch (split-pair outputs) */
    GemmJobs J = {};
    const float* As[7]  = {x, x, x, wq, wk, wv, wo};
    long sAbs[7]        = {(long)SEQ*DIM, (long)SEQ*DIM, (long)SEQ*DIM, 0, 0, 0, 0};
    int  whichB[7]      = {0, 1, 2, 0, 1, 2, 3};
    uint32_t* Cs[7]     = {dASB + 0L*BATCH*SEQ*SK, dASB + 1L*BATCH*SEQ*SK,
                           dASB + 2L*BATCH*SEQ*SK, dTqB, dTkB, dTvB, dToB};
    long sCbs[7]        = {(long)SEQ*SK, (long)SEQ*SK, (long)SEQ*SK,
                           (long)DIM*SK, (long)KVD*SK, (long)KVD*SK, (long)DIM*SK};
    int  mt[7]          = {16, 16, 16, 16, 8, 8, 16};
    float al[7]         = {1.0f/SK, 1.0f/SK, 1.0f/SK, 1.0f, 1.0f, 1.0f, 1.0f};
    for (int i = 0; i < 7; i++) {
        J.A[i] = As[i]; J.sAb[i] = sAbs[i];
        J.B[i] = dSB + (long)whichB[i]*SBwb; J.sBb[i] = SBw;
        J.C[i] = Cs[i]; J.sCb[i] = sCbs[i];
        J.mtiles[i] = mt[i]; J.alpha[i] = al[i];
    }
    k_gemm_mma<<<dim3(16, 7, BATCH), blk, GEMM_SMEM>>>(J);

    /* q/k/v projections (MMA, fused; RoPE + V pre-transpose epilogues) */
    k_proj_mma<<<dim3(16, 64, BATCH), blk, PROJ_SMEM>>>(fr, out, 0);

    /* causal flash attention (BN=128, pre-transposed V) -> g_ao */
    k_flash<<<dim3(SEQ/128, NH, BATCH), blk, FLASH_SMEM>>>();

    /* AS_o = attn_out @ So / 64 */
    GemmJobs J2 = {};
    J2.A[0] = dAo;  J2.sAb[0] = (long)SEQ*DIM;
    J2.B[0] = dSB + 3L*SBwb; J2.sBb[0] = SBw;
    J2.C[0] = dASoB; J2.sCb[0] = (long)SEQ*SK;
    J2.mtiles[0] = 16; J2.alpha[0] = 1.0f/SK;
    k_gemm_mma<<<dim3(16, 1, BATCH), blk, GEMM_SMEM>>>(J2);

    /* final = AS_o @ To^T -> d_out */
    k_proj_mma<<<dim3(16, 32, BATCH), blk, PROJ_SMEM>>>(fr, out, 1);
}

// round 15
// speedup vs baseline: 1.4930x; 1.4930x over previous
#include <cuda_runtime.h>
#include <cuda_bf16.h>
#include <math.h>
#include <stdint.h>

#define BATCH 2
#define SEQ   2048
#define DIM   2048
#define NH    16
#define NKV   8
#define HD    128
#define KVD   (NKV*HD)
#define SK    64
#define INV_SQRT_HD 0.08838834764831845f  /* 1/sqrt(128) */

/* ------------------------- scratch (static device) ------------------------ */
/* split-pair (bf16 hi/lo interleaved) intermediates, 64 words per row */
__device__ uint32_t g_ASB [(size_t)3*BATCH*SEQ*SK];
__device__ uint32_t g_ASoB[(size_t)BATCH*SEQ*SK];
__device__ uint32_t g_TqB [(size_t)BATCH*DIM*SK];
__device__ uint32_t g_TkB [(size_t)BATCH*KVD*SK];
__device__ uint32_t g_TvB [(size_t)BATCH*KVD*SK];
__device__ uint32_t g_ToB [(size_t)BATCH*DIM*SK];
/* fp32 tensors */
__device__ float g_q  [(size_t)BATCH*NH *SEQ*HD];
__device__ float g_k  [(size_t)BATCH*NKV*SEQ*HD];
__device__ float g_vT [(size_t)BATCH*NKV*HD*SEQ];   /* [b,kvh][d][s] */
__device__ float g_ao [(size_t)BATCH*SEQ*DIM];
/* pre-split sketch matrices, MMA-B layout: [which][b][n=64][k word] */
__device__ uint32_t g_SB [(size_t)4*BATCH*64*2048];

/* ---------------------- bf16 split / mma helpers ---------------------- */
__device__ __forceinline__ uint32_t pack_bf16(float a, float b) {
    __nv_bfloat162 t = __floats2bfloat162_rn(a, b);
    return *reinterpret_cast<uint32_t*>(&t);
}
__device__ __forceinline__ void split2(float a, float b,
                                       uint32_t& hi, uint32_t& lo) {
    float ha = __bfloat162float(__float2bfloat16_rn(a));
    float hb = __bfloat162float(__float2bfloat16_rn(b));
    hi = pack_bf16(ha, hb);
    lo = pack_bf16(a - ha, b - hb);
}
__device__ __forceinline__ void mma_bf16(float* c, const uint32_t* a,
                                         uint32_t b0, uint32_t b1) {
    asm volatile(
        "mma.sync.aligned.m16n8k16.row.col.f32.bf16.bf16.f32 "
        "{%0,%1,%2,%3}, {%4,%5,%6,%7}, {%8,%9}, {%0,%1,%2,%3};"
        : "+f"(c[0]), "+f"(c[1]), "+f"(c[2]), "+f"(c[3])
        : "r"(a[0]), "r"(a[1]), "r"(a[2]), "r"(a[3]), "r"(b0), "r"(b1));
}
__device__ __forceinline__ void mma3b(float* c,
                                      const uint32_t* ah, const uint32_t* al,
                                      uint32_t bh0, uint32_t bh1,
                                      uint32_t bl0, uint32_t bl1) {
    mma_bf16(c, al, bh0, bh1);
    mma_bf16(c, ah, bl0, bl1);
    mma_bf16(c, ah, bh0, bh1);
}

/* =====================================================================
 * k_splitS: pre-split all four sketch matrices into MMA-B layout.
 * =====================================================================*/
__global__ void k_splitS(const float* __restrict__ Sq, const float* __restrict__ Sk,
                         const float* __restrict__ Sv, const float* __restrict__ So)
{
    int t = blockIdx.x*256 + threadIdx.x;
    int jq = t & 1023;
    int n  = (t >> 10) & 63;
    int b  = (t >> 16) & 1;
    int which = t >> 17;
    const float* S = (which==0?Sq:which==1?Sk:which==2?Sv:So) + (size_t)b*DIM*SK;
    float f0 = S[(size_t)(2*jq  )*SK + n];
    float f1 = S[(size_t)(2*jq+1)*SK + n];
    uint32_t hi, lo;
    split2(f0, f1, hi, lo);
    *(uint2*)(g_SB + (((size_t)which*BATCH + b)*64 + n)*2048 + (size_t)jq*2) =
        make_uint2(hi, lo);
}

/* =====================================================================
 * k_gemm_mma: multi-job GEMM, C = alpha * A(Mx2048) @ B^T (N=64).
 *   Double-buffered, register-prefetched. Split-pair epilogue.
 * =====================================================================*/
#define GAS 40
#define GBUF ((128 + 64) * GAS)
#define GEMM_SMEM (2 * GBUF * 4)

struct GemmJobs {
    const float*    A[7];
    const uint32_t* B[7];
    uint32_t*       C[7];
    long  sAb[7];
    long  sBb[7];
    long  sCb[7];   /* words */
    int   mtiles[7];
    float alpha[7];
};

__global__ void __launch_bounds__(256, 1) k_gemm_mma(GemmJobs J)
{
    extern __shared__ uint32_t smg[];
    int job = blockIdx.y, b = blockIdx.z;
    if ((int)blockIdx.x >= J.mtiles[job]) return;
    int tm0 = blockIdx.x * 128;
    const float*    A = J.A[job] + (size_t)b*J.sAb[job] + (size_t)tm0*DIM;
    const uint32_t* B = J.B[job] + (size_t)b*J.sBb[job];
    uint32_t*       C = J.C[job] + (size_t)b*J.sCb[job] + (size_t)tm0*SK;
    float alpha = J.alpha[job];

    int tid = threadIdx.x, lane = tid & 31, w = tid >> 5;
    int gid = lane >> 2, qd = lane & 3;
    int m0 = w*16;
    int ar = tid >> 1, ahalf = tid & 1;
    int bn = tid >> 3, bj4 = tid & 7;

    float acc[8][4] = {};
    float4 av[4];
    uint4  bv[2];

    {
        const float* Ap = A + (size_t)ar*DIM + ahalf*16;
        av[0] = ((const float4*)Ap)[0]; av[1] = ((const float4*)Ap)[1];
        av[2] = ((const float4*)Ap)[2]; av[3] = ((const float4*)Ap)[3];
        bv[0] = *(const uint4*)(B + (size_t)bn*2048 + bj4*4);
        bv[1] = *(const uint4*)(B + (size_t)(bn+32)*2048 + bj4*4);
    }
    {
        uint32_t* dA = smg;
        uint32_t* dB = smg + 128*GAS;
        #pragma unroll
        for (int i = 0; i < 4; i++) {
            uint32_t h01, l01, h23, l23;
            split2(av[i].x, av[i].y, h01, l01);
            split2(av[i].z, av[i].w, h23, l23);
            *(uint4*)(dA + (size_t)ar*GAS + ahalf*16 + i*4) =
                make_uint4(h01, l01, h23, l23);
        }
        *(uint4*)(dB + (size_t)bn*GAS + bj4*4)      = bv[0];
        *(uint4*)(dB + (size_t)(bn+32)*GAS + bj4*4) = bv[1];
    }
    __syncthreads();

    for (int it = 0; it < 64; it++) {
        uint32_t* sA = smg + (it & 1)*GBUF;
        uint32_t* sB = sA + 128*GAS;
        bool more = (it + 1 < 64);
        if (more) {
            int k0 = (it + 1)*32;
            const float* Ap = A + (size_t)ar*DIM + k0 + ahalf*16;
            av[0] = ((const float4*)Ap)[0]; av[1] = ((const float4*)Ap)[1];
            av[2] = ((const float4*)Ap)[2]; av[3] = ((const float4*)Ap)[3];
            bv[0] = *(const uint4*)(B + (size_t)bn*2048 + k0 + bj4*4);
            bv[1] = *(const uint4*)(B + (size_t)(bn+32)*2048 + k0 + bj4*4);
        }
        #pragma unroll
        for (int ks = 0; ks < 2; ks++) {
            uint2 qa0 = *(const uint2*)(sA + (size_t)(m0+gid  )*GAS + (8*ks+qd  )*2);
            uint2 qa1 = *(const uint2*)(sA + (size_t)(m0+gid+8)*GAS + (8*ks+qd  )*2);
            uint2 qa2 = *(const uint2*)(sA + (size_t)(m0+gid  )*GAS + (8*ks+qd+4)*2);
            uint2 qa3 = *(const uint2*)(sA + (size_t)(m0+gid+8)*GAS + (8*ks+qd+4)*2);
            uint32_t ah[4] = {qa0.x, qa1.x, qa2.x, qa3.x};
            uint32_t al[4] = {qa0.y, qa1.y, qa2.y, qa3.y};
            #pragma unroll
            for (int nt = 0; nt < 8; nt++) {
                uint2 kb0 = *(const uint2*)(sB + (size_t)(nt*8+gid)*GAS + (8*ks+qd  )*2);
                uint2 kb1 = *(const uint2*)(sB + (size_t)(nt*8+gid)*GAS + (8*ks+qd+4)*2);
                mma3b(acc[nt], ah, al, kb0.x, kb1.x, kb0.y, kb1.y);
            }
        }
        if (more) {
            uint32_t* dA = smg + ((it + 1) & 1)*GBUF;
            uint32_t* dB = dA + 128*GAS;
            #pragma unroll
            for (int i = 0; i < 4; i++) {
                uint32_t h01, l01, h23, l23;
                split2(av[i].x, av[i].y, h01, l01);
                split2(av[i].z, av[i].w, h23, l23);
                *(uint4*)(dA + (size_t)ar*GAS + ahalf*16 + i*4) =
                    make_uint4(h01, l01, h23, l23);
            }
            *(uint4*)(dB + (size_t)bn*GAS + bj4*4)      = bv[0];
            *(uint4*)(dB + (size_t)(bn+32)*GAS + bj4*4) = bv[1];
            __syncthreads();
        }
    }

    /* ---- epilogue: write split-pair layout ---- */
    #pragma unroll
    for (int nt = 0; nt < 8; nt++) {
        uint2 u0, u1;
        split2(acc[nt][0]*alpha, acc[nt][1]*alpha, u0.x, u0.y);
        split2(acc[nt][2]*alpha, acc[nt][3]*alpha, u1.x, u1.y);
        *(uint2*)(C + (size_t)(m0+gid  )*SK + (nt*4+qd)*2) = u0;
        *(uint2*)(C + (size_t)(m0+gid+8)*SK + (nt*4+qd)*2) = u1;
    }
}

/* =====================================================================
 * k_proj_mma: X = ASs @ Ts^T via 3-MMA bf16 split, K=64 (4 k-steps).
 *   128x64 tile, 8 warps. Inputs pre-split. Epilogues:
 *     mode 0/1: RoPE -> g_q/g_k [b,h][s][d]
 *     mode 2:   smem transpose -> g_vT [b,kvh][d][s]
 *     mode 3:   d_out [b][s][m]
 * =====================================================================*/
#define PJS 72
#define PROJ_SMEM ((128*PJS + 64*PJS) * 4)

__global__ void __launch_bounds__(256, 1) k_proj_mma(
    const float* __restrict__ freqs, float* __restrict__ dout, int phase)
{
    extern __shared__ uint32_t smp[];
    uint32_t* sA = smp;
    uint32_t* sB = smp + 128*PJS;

    int b = blockIdx.z, y = blockIdx.y;
    int mode, mt;
    if (phase)       { mode = 3; mt = y; }
    else if (y < 32) { mode = 0; mt = y; }
    else if (y < 48) { mode = 1; mt = y - 32; }
    else             { mode = 2; mt = y - 48; }
    int s0 = blockIdx.x * 128, m0g = mt * 64;

    const uint32_t* Asrc;
    const uint32_t* Bsrc;
    if      (mode == 0) { Asrc = g_ASB + ((size_t)0*BATCH + b)*SEQ*SK; Bsrc = g_TqB + (size_t)b*DIM*SK; }
    else if (mode == 1) { Asrc = g_ASB + ((size_t)1*BATCH + b)*SEQ*SK; Bsrc = g_TkB + (size_t)b*KVD*SK; }
    else if (mode == 2) { Asrc = g_ASB + ((size_t)2*BATCH + b)*SEQ*SK; Bsrc = g_TvB + (size_t)b*KVD*SK; }
    else                { Asrc = g_ASoB + (size_t)b*SEQ*SK;            Bsrc = g_ToB + (size_t)b*DIM*SK; }

    int tid = threadIdx.x, lane = tid & 31, w = tid >> 5;
    int gid = lane >> 2, qd = lane & 3;
    int m0 = w*16;

    #pragma unroll
    for (int it = 0; it < 8; it++) {
        int idx = tid + it*256;
        int r = idx >> 4, c4 = (idx & 15)*4;
        *(uint4*)(sA + (size_t)r*PJS + c4) =
            *(const uint4*)(Asrc + (size_t)(s0 + r)*SK + c4);
    }
    #pragma unroll
    for (int it = 0; it < 4; it++) {
        int idx = tid + it*256;
        int r = idx >> 4, c4 = (idx & 15)*4;
        *(uint4*)(sB + (size_t)r*PJS + c4) =
            *(const uint4*)(Bsrc + (size_t)(m0g + r)*SK + c4);
    }
    __syncthreads();

    float acc[8][4] = {};
    #pragma unroll
    for (int ks = 0; ks < 4; ks++) {
        uint2 qa0 = *(const uint2*)(sA + (size_t)(m0+gid  )*PJS + (8*ks+qd  )*2);
        uint2 qa1 = *(const uint2*)(sA + (size_t)(m0+gid+8)*PJS + (8*ks+qd  )*2);
        uint2 qa2 = *(const uint2*)(sA + (size_t)(m0+gid  )*PJS + (8*ks+qd+4)*2);
        uint2 qa3 = *(const uint2*)(sA + (size_t)(m0+gid+8)*PJS + (8*ks+qd+4)*2);
        uint32_t ah[4] = {qa0.x, qa1.x, qa2.x, qa3.x};
        uint32_t al[4] = {qa0.y, qa1.y, qa2.y, qa3.y};
        #pragma unroll
        for (int nt = 0; nt < 8; nt++) {
            uint2 kb0 = *(const uint2*)(sB + (size_t)(nt*8+gid)*PJS + (8*ks+qd  )*2);
            uint2 kb1 = *(const uint2*)(sB + (size_t)(nt*8+gid)*PJS + (8*ks+qd+4)*2);
            mma3b(acc[nt], ah, al, kb0.x, kb1.x, kb0.y, kb1.y);
        }
    }

    if (mode == 3) {
        #pragma unroll
        for (int nt = 0; nt < 8; nt++) {
            int c = nt*8 + 2*qd;
            *(float2*)(dout + ((size_t)b*SEQ + s0+m0+gid  )*DIM + m0g + c) =
                make_float2(acc[nt][0], acc[nt][1]);
            *(float2*)(dout + ((size_t)b*SEQ + s0+m0+gid+8)*DIM + m0g + c) =
                make_float2(acc[nt][2], acc[nt][3]);
        }
    } else if (mode == 2) {
        __syncthreads();
        float* st = (float*)smp;   /* [64][132] */
        #pragma unroll
        for (int nt = 0; nt < 8; nt++) {
            int c = nt*8 + 2*qd;
            st[(size_t)(c  )*132 + m0+gid  ] = acc[nt][0];
            st[(size_t)(c+1)*132 + m0+gid  ] = acc[nt][1];
            st[(size_t)(c  )*132 + m0+gid+8] = acc[nt][2];
            st[(size_t)(c+1)*132 + m0+gid+8] = acc[nt][3];
        }
        __syncthreads();
        int h = m0g >> 7, d0b = m0g & 127;
        float* Vt = g_vT + ((size_t)(b*NKV + h)*HD + d0b)*SEQ;
        #pragma unroll
        for (int it = 0; it < 8; it++) {
            int slot = tid + it*256;
            int d = slot >> 5, s4 = (slot & 31)*4;
            float4 v = *(float4*)(st + (size_t)d*132 + s4);
            *(float4*)(Vt + (size_t)d*SEQ + s0 + s4) = v;
        }
    } else {
        int h = m0g >> 7;
        float* base = (mode == 0) ? g_q + ((size_t)(b*NH  + h))*SEQ*HD
                                  : g_k + ((size_t)(b*NKV + h))*SEQ*HD;
        #pragma unroll
        for (int nt = 0; nt < 8; nt++) {
            int c  = nt*8 + 2*qd;
            int d0 = (m0g & 127) + c;
            int dh = d0 >> 1;
            int srA = s0 + m0 + gid, srB = srA + 8;
            const float* fA = freqs + ((size_t)srA*64 + dh)*2;
            float c0 = fA[0], n0 = fA[1];
            *(float2*)(base + (size_t)srA*HD + d0) =
                make_float2(acc[nt][0]*n0 - acc[nt][1]*c0,
                            acc[nt][0]*c0 + acc[nt][1]*n0);
            const float* fB = freqs + ((size_t)srB*64 + dh)*2;
            float c1 = fB[0], n1 = fB[1];
            *(float2*)(base + (size_t)srB*HD + d0) =
                make_float2(acc[nt][2]*n1 - acc[nt][3]*c1,
                            acc[nt][2]*c1 + acc[nt][3]*n1);
        }
    }
}

/* =====================================================================
 * k_flash: causal flash attention, 2-term bf16 split, mma m16n8k16.
 *   BM=128, BN=64 (reverted — register budget), 8 warps.
 *   V read pre-transposed from g_vT (no staging pass).
 *   P has its own buffer -> 2 barriers/tile (load-sync, end-sync).
 *   smem: sQ[128][136], sK[64][136], sV[128][72], sP[128][72].
 *   grid (SEQ/128, NH, B); GQA kv head = h>>1; tail-first scheduling.
 * =====================================================================*/
#define QS 136
#define KS 136
#define VS 72
#define PS 72
#define SQ_OFF  0
#define SK_OFF  (128*QS)               /* 17408 */
#define SV_OFF  (SK_OFF + 64*KS)       /* 26112 */
#define SP_OFF  (SV_OFF + 128*VS)      /* 35328 */
#define FLASH_WORDS (SP_OFF + 128*PS)  /* 44544 */
#define FLASH_SMEM  (FLASH_WORDS * 4)  /* 178176 B */

__global__ void __launch_bounds__(256, 1) k_flash()
{
    extern __shared__ uint32_t smw[];
    uint32_t* sQ = smw + SQ_OFF;
    uint32_t* sK = smw + SK_OFF;
    uint32_t* sV = smw + SV_OFF;
    uint32_t* sP = smw + SP_OFF;

    int tid = threadIdx.x, lane = tid & 31, w = tid >> 5;
    int qt = (int)gridDim.x - 1 - (int)blockIdx.x;
    int h = blockIdx.y, b = blockIdx.z;
    int gid = lane >> 2, qd = lane & 3;

    const float* Qg = g_q  + ((size_t)(b*NH  + h))     *SEQ*HD + (size_t)qt*128*HD;
    const float* Kb = g_k  + ((size_t)(b*NKV + (h>>1)))*SEQ*HD;
    const float* Vt = g_vT + ((size_t)(b*NKV + (h>>1)))*HD*SEQ;

    /* ---- load Q tile: scale, split ---- */
    #pragma unroll
    for (int it = 0; it < 16; it++) {
        int slot = tid + it*256;
        int r = slot >> 5, c4 = (slot & 31) * 4;
        float4 v = *(const float4*)(Qg + (size_t)r*HD + c4);
        uint32_t h01, l01, h23, l23;
        split2(v.x*INV_SQRT_HD, v.y*INV_SQRT_HD, h01, l01);
        split2(v.z*INV_SQRT_HD, v.w*INV_SQRT_HD, h23, l23);
        *(uint4*)(sQ + (size_t)r*QS + c4) = make_uint4(h01, l01, h23, l23);
    }

    int m0 = w*16;
    float o[16][4] = {};
    float miA = -1e30f, miB = -1e30f, liA = 0.f, liB = 0.f;
    int row_min = qt*128 + w*16;
    int row_max = row_min + 15;
    int nkt = 2*qt + 2;

    for (int kt = 0; kt < nkt; kt++) {
        const float* Kg = Kb + (size_t)kt*64*HD;
        /* ---- K: load + split (64 rows x 128 d) ---- */
        #pragma unroll
        for (int it = 0; it < 8; it++) {
            int slot = tid + it*256;
            int r = slot >> 5, c4 = (slot & 31) * 4;
            float4 kv = *(const float4*)(Kg + (size_t)r*HD + c4);
            uint32_t h01, l01, h23, l23;
            split2(kv.x, kv.y, h01, l01);
            split2(kv.z, kv.w, h23, l23);
            *(uint4*)(sK + (size_t)r*KS + c4) = make_uint4(h01, l01, h23, l23);
        }
        /* ---- V: load pre-transposed [d][p], split pairs (128 d x 64 p) ---- */
        #pragma unroll
        for (int it = 0; it < 8; it++) {
            int slot = tid + it*256;
            int d = slot >> 4, p4 = (slot & 15) * 4;
            float4 vv = *(const float4*)(Vt + (size_t)d*SEQ + kt*64 + p4);
            uint32_t h01, l01, h23, l23;
            split2(vv.x, vv.y, h01, l01);
            split2(vv.z, vv.w, h23, l23);
            *(uint4*)(sV + (size_t)d*VS + p4) = make_uint4(h01, l01, h23, l23);
        }
        __syncthreads();

        bool active = (kt*64 <= row_max);
        if (active) {
            /* ---- S = Q K^T ---- */
            float s[8][4] = {};
            #pragma unroll
            for (int ks = 0; ks < 8; ks++) {
                uint2 qa0 = *(const uint2*)(sQ + (size_t)(m0+gid  )*QS + (8*ks+qd  )*2);
                uint2 qa1 = *(const uint2*)(sQ + (size_t)(m0+gid+8)*QS + (8*ks+qd  )*2);
                uint2 qa2 = *(const uint2*)(sQ + (size_t)(m0+gid  )*QS + (8*ks+qd+4)*2);
                uint2 qa3 = *(const uint2*)(sQ + (size_t)(m0+gid+8)*QS + (8*ks+qd+4)*2);
                uint32_t ah[4] = {qa0.x, qa1.x, qa2.x, qa3.x};
                uint32_t al[4] = {qa0.y, qa1.y, qa2.y, qa3.y};
                #pragma unroll
                for (int nt = 0; nt < 8; nt++) {
                    uint2 kb0 = *(const uint2*)(sK + (size_t)(nt*8+gid)*KS + (8*ks+qd  )*2);
                    uint2 kb1 = *(const uint2*)(sK + (size_t)(nt*8+gid)*KS + (8*ks+qd+4)*2);
                    mma3b(s[nt], ah, al, kb0.x, kb1.x, kb0.y, kb1.y);
                }
            }

            /* ---- causal mask (partial tiles only) ---- */
            if (kt*64 + 63 > row_min) {
                int rA = row_min + gid, rB = rA + 8;
                #pragma unroll
                for (int nt = 0; nt < 8; nt++) {
                    int c0 = kt*64 + nt*8 + 2*qd;
                    if (c0     > rA) s[nt][0] = -1e30f;
                    if (c0 + 1 > rA) s[nt][1] = -1e30f;
                    if (c0     > rB) s[nt][2] = -1e30f;
                    if (c0 + 1 > rB) s[nt][3] = -1e30f;
                }
            }

            /* ---- online softmax ---- */
            float mA = -1e30f, mB = -1e30f;
            #pragma unroll
            for (int nt = 0; nt < 8; nt++) {
                mA = fmaxf(mA, fmaxf(s[nt][0], s[nt][1]));
                mB = fmaxf(mB, fmaxf(s[nt][2], s[nt][3]));
            }
            mA = fmaxf(mA, __shfl_xor_sync(0xffffffffu, mA, 1));
            mA = fmaxf(mA, __shfl_xor_sync(0xffffffffu, mA, 2));
            mB = fmaxf(mB, __shfl_xor_sync(0xffffffffu, mB, 1));
            mB = fmaxf(mB, __shfl_xor_sync(0xffffffffu, mB, 2));
            float newmA = fmaxf(miA, mA), newmB = fmaxf(miB, mB);
            float alA = __expf(miA - newmA), alB = __expf(miB - newmB);
            float sumA = 0.f, sumB = 0.f;
            #pragma unroll
            for (int nt = 0; nt < 8; nt++) {
                s[nt][0] = __expf(s[nt][0] - newmA);
                s[nt][1] = __expf(s[nt][1] - newmA);
                s[nt][2] = __expf(s[nt][2] - newmB);
                s[nt][3] = __expf(s[nt][3] - newmB);
                sumA += s[nt][0] + s[nt][1];
                sumB += s[nt][2] + s[nt][3];
            }
            sumA += __shfl_xor_sync(0xffffffffu, sumA, 1);
            sumA += __shfl_xor_sync(0xffffffffu, sumA, 2);
            sumB += __shfl_xor_sync(0xffffffffu, sumB, 1);
            sumB += __shfl_xor_sync(0xffffffffu, sumB, 2);
            liA = liA*alA + sumA;  miA = newmA;
            liB = liB*alB + sumB;  miB = newmB;

            /* ---- rescale O ---- */
            #pragma unroll
            for (int nt = 0; nt < 16; nt++) {
                o[nt][0] *= alA; o[nt][1] *= alA;
                o[nt][2] *= alB; o[nt][3] *= alB;
            }

            /* ---- store P split (own warp's rows only; own buffer) ---- */
            #pragma unroll
            for (int nt = 0; nt < 8; nt++) {
                uint32_t hA, lA, hB, lB;
                split2(s[nt][0], s[nt][1], hA, lA);
                split2(s[nt][2], s[nt][3], hB, lB);
                *(uint2*)(sP + (size_t)(m0+gid  )*PS + (nt*4+qd)*2) = make_uint2(hA, lA);
                *(uint2*)(sP + (size_t)(m0+gid+8)*PS + (nt*4+qd)*2) = make_uint2(hB, lB);
            }
            __syncwarp();

            /* ---- O += P V ---- */
            #pragma unroll
            for (int ks = 0; ks < 4; ks++) {
                uint2 pa0 = *(const uint2*)(sP + (size_t)(m0+gid  )*PS + (8*ks+qd  )*2);
                uint2 pa1 = *(const uint2*)(sP + (size_t)(m0+gid+8)*PS + (8*ks+qd  )*2);
                uint2 pa2 = *(const uint2*)(sP + (size_t)(m0+gid  )*PS + (8*ks+qd+4)*2);
                uint2 pa3 = *(const uint2*)(sP + (size_t)(m0+gid+8)*PS + (8*ks+qd+4)*2);
                uint32_t ph[4] = {pa0.x, pa1.x, pa2.x, pa3.x};
                uint32_t pl[4] = {pa0.y, pa1.y, pa2.y, pa3.y};
                #pragma unroll
                for (int nt = 0; nt < 16; nt++) {
                    uint2 vb0 = *(const uint2*)(sV + (size_t)(nt*8+gid)*VS + (8*ks+qd  )*2);
                    uint2 vb1 = *(const uint2*)(sV + (size_t)(nt*8+gid)*VS + (8*ks+qd+4)*2);
                    mma3b(o[nt], ph, pl, vb0.x, vb1.x, vb0.y, vb1.y);
                }
            }
        }
        __syncthreads();
    }

    /* ---- epilogue: O/l -> g_ao [b, s, h*HD + d] ---- */
    float invA = 1.0f / liA, invB = 1.0f / liB;
    float* Og = g_ao + ((size_t)b*SEQ + (size_t)qt*128)*DIM + (size_t)h*HD;
    #pragma unroll
    for (int nt = 0; nt < 16; nt++) {
        int c = nt*8 + 2*qd;
        float2 vA = make_float2(o[nt][0]*invA, o[nt][1]*invA);
        float2 vB = make_float2(o[nt][2]*invB, o[nt][3]*invB);
        *(float2*)(Og + (size_t)(m0 + gid)    *DIM + c) = vA;
        *(float2*)(Og + (size_t)(m0 + gid + 8)*DIM + c) = vB;
    }
}

/* ========================= launch ========================= */
extern "C" void kernel_launch(void* const* d_in, const int* in_sizes, int n_in,
                              void* d_out, int out_size)
{
    const float* x  = (const float*)d_in[0];
    const float* wq = (const float*)d_in[1];
    const float* wk = (const float*)d_in[2];
    const float* wv = (const float*)d_in[3];
    const float* wo = (const float*)d_in[4];
    const float* Sq = (const float*)d_in[5];
    const float* Sk = (const float*)d_in[6];
    const float* Sv = (const float*)d_in[7];
    const float* So = (const float*)d_in[8];
    const float* fr = (const float*)d_in[9];
    float* out = (float*)d_out;

    cudaFuncSetAttribute(k_flash, cudaFuncAttributeMaxDynamicSharedMemorySize,
                         FLASH_SMEM);
    cudaFuncSetAttribute(k_gemm_mma, cudaFuncAttributeMaxDynamicSharedMemorySize,
                         GEMM_SMEM);
    cudaFuncSetAttribute(k_proj_mma, cudaFuncAttributeMaxDynamicSharedMemorySize,
                         PROJ_SMEM);

    uint32_t* dSB;   cudaGetSymbolAddress((void**)&dSB,   g_SB);
    uint32_t* dASB;  cudaGetSymbolAddress((void**)&dASB,  g_ASB);
    uint32_t* dASoB; cudaGetSymbolAddress((void**)&dASoB, g_ASoB);
    uint32_t* dTqB;  cudaGetSymbolAddress((void**)&dTqB,  g_TqB);
    uint32_t* dTkB;  cudaGetSymbolAddress((void**)&dTkB,  g_TkB);
    uint32_t* dTvB;  cudaGetSymbolAddress((void**)&dTvB,  g_TvB);
    uint32_t* dToB;  cudaGetSymbolAddress((void**)&dToB,  g_ToB);
    float*    dAo;   cudaGetSymbolAddress((void**)&dAo,   g_ao);

    dim3 blk(256);
    const long SBw  = 64L*2048;
    const long SBwb = (long)BATCH*SBw;

    /* pre-split sketches into MMA-B layout */
    k_splitS<<<2048, blk>>>(Sq, Sk, Sv, So);

    /* all 7 pre-attention GEMMs in ONE launch (split-pair outputs) */
    GemmJobs J = {};
    const float* As[7]  = {x, x, x, wq, wk, wv, wo};
    long sAbs[7]        = {(long)SEQ*DIM, (long)SEQ*DIM, (long)SEQ*DIM, 0, 0, 0, 0};
    int  whichB[7]      = {0, 1, 2, 0, 1, 2, 3};
    uint32_t* Cs[7]     = {dASB + 0L*BATCH*SEQ*SK, dASB + 1L*BATCH*SEQ*SK,
                           dASB + 2L*BATCH*SEQ*SK, dTqB, dTkB, dTvB, dToB};
    long sCbs[7]        = {(long)SEQ*SK, (long)SEQ*SK, (long)SEQ*SK,
                           (long)DIM*SK, (long)KVD*SK, (long)KVD*SK, (long)DIM*SK};
    int  mt[7]          = {16, 16, 16, 16, 8, 8, 16};
    float al[7]         = {1.0f/SK, 1.0f/SK, 1.0f/SK, 1.0f, 1.0f, 1.0f, 1.0f};
    for (int i = 0; i < 7; i++) {
        J.A[i] = As[i]; J.sAb[i] = sAbs[i];
        J.B[i] = dSB + (long)whichB[i]*SBwb; J.sBb[i] = SBw;
        J.C[i] = Cs[i]; J.sCb[i] = sCbs[i];
        J.mtiles[i] = mt[i]; J.alpha[i] = al[i];
    }
    k_gemm_mma<<<dim3(16, 7, BATCH), blk, GEMM_SMEM>>>(J);

    /* q/k/v projections (MMA, fused; RoPE + V pre-transpose epilogues) */
    k_proj_mma<<<dim3(16, 64, BATCH), blk, PROJ_SMEM>>>(fr, out, 0);

    /* causal flash attention (BN=64, pre-transposed V) -> g_ao */
    k_flash<<<dim3(SEQ/128, NH, BATCH), blk, FLASH_SMEM>>>();

    /* AS_o = attn_out @ So / 64 */
    GemmJobs J2 = {};
    J2.A[0] = dAo;  J2.sAb[0] = (long)SEQ*DIM;
    J2.B[0] = dSB + 3L*SBwb; J2.sBb[0] = SBw;
    J2.C[0] = dASoB; J2.sCb[0] = (long)SEQ*SK;
    J2.mtiles[0] = 16; J2.alpha[0] = 1.0f/SK;
    k_gemm_mma<<<dim3(16, 1, BATCH), blk, GEMM_SMEM>>>(J2);

    /* final = AS_o @ To^T -> d_out */
    k_proj_mma<<<dim3(16, 32, BATCH), blk, PROJ_SMEM>>>(fr, out, 1);
}

// round 17
// speedup vs baseline: 1.5905x; 1.0653x over previous
#include <cuda_runtime.h>
#include <cuda_bf16.h>
#include <math.h>
#include <stdint.h>

#define BATCH 2
#define SEQ   2048
#define DIM   2048
#define NH    16
#define NKV   8
#define HD    128
#define KVD   (NKV*HD)
#define SK    64
#define INV_SQRT_HD 0.08838834764831845f  /* 1/sqrt(128) */

/* ------------------------- scratch (static device) ------------------------ */
/* split-pair (bf16 hi/lo interleaved) intermediates, 64 words per row */
__device__ uint32_t g_ASB [(size_t)3*BATCH*SEQ*SK];
__device__ uint32_t g_ASoB[(size_t)BATCH*SEQ*SK];
__device__ uint32_t g_TqB [(size_t)BATCH*DIM*SK];
__device__ uint32_t g_TkB [(size_t)BATCH*KVD*SK];
__device__ uint32_t g_TvB [(size_t)BATCH*KVD*SK];
__device__ uint32_t g_ToB [(size_t)BATCH*DIM*SK];
/* pre-split q/k/v in flash smem layouts (1 word per element) */
__device__ uint32_t g_qB [(size_t)BATCH*NH *SEQ*HD];   /* [b,h][s][d-pair words], pre-scaled */
__device__ uint32_t g_kB [(size_t)BATCH*NKV*SEQ*HD];   /* [b,kvh][s][d-pair words] */
__device__ uint32_t g_vTB[(size_t)BATCH*NKV*HD*SEQ];   /* [b,kvh][d][s-pair words] */
__device__ float    g_ao [(size_t)BATCH*SEQ*DIM];
/* pre-split sketch matrices, MMA-B layout: [which][b][n=64][k word] */
__device__ uint32_t g_SB [(size_t)4*BATCH*64*2048];

/* ---------------------- bf16 split / mma / cp.async helpers ---------------------- */
__device__ __forceinline__ uint32_t pack_bf16(float a, float b) {
    __nv_bfloat162 t = __floats2bfloat162_rn(a, b);
    return *reinterpret_cast<uint32_t*>(&t);
}
__device__ __forceinline__ void split2(float a, float b,
                                       uint32_t& hi, uint32_t& lo) {
    float ha = __bfloat162float(__float2bfloat16_rn(a));
    float hb = __bfloat162float(__float2bfloat16_rn(b));
    hi = pack_bf16(ha, hb);
    lo = pack_bf16(a - ha, b - hb);
}
__device__ __forceinline__ void mma_bf16(float* c, const uint32_t* a,
                                         uint32_t b0, uint32_t b1) {
    asm volatile(
        "mma.sync.aligned.m16n8k16.row.col.f32.bf16.bf16.f32 "
        "{%0,%1,%2,%3}, {%4,%5,%6,%7}, {%8,%9}, {%0,%1,%2,%3};"
        : "+f"(c[0]), "+f"(c[1]), "+f"(c[2]), "+f"(c[3])
        : "r"(a[0]), "r"(a[1]), "r"(a[2]), "r"(a[3]), "r"(b0), "r"(b1));
}
__device__ __forceinline__ void mma3b(float* c,
                                      const uint32_t* ah, const uint32_t* al,
                                      uint32_t bh0, uint32_t bh1,
                                      uint32_t bl0, uint32_t bl1) {
    mma_bf16(c, al, bh0, bh1);
    mma_bf16(c, ah, bl0, bl1);
    mma_bf16(c, ah, bh0, bh1);
}
__device__ __forceinline__ void cp16(uint32_t smem_dst, const void* gsrc) {
    asm volatile("cp.async.cg.shared.global [%0], [%1], 16;"
                 :: "r"(smem_dst), "l"(gsrc));
}
#define CP_COMMIT() asm volatile("cp.async.commit_group;")
#define CP_WAIT0()  asm volatile("cp.async.wait_group 0;" ::: "memory")

/* =====================================================================
 * k_splitS: pre-split all four sketch matrices into MMA-B layout.
 * =====================================================================*/
__global__ void k_splitS(const float* __restrict__ Sq, const float* __restrict__ Sk,
                         const float* __restrict__ Sv, const float* __restrict__ So)
{
    int t = blockIdx.x*256 + threadIdx.x;
    int jq = t & 1023;
    int n  = (t >> 10) & 63;
    int b  = (t >> 16) & 1;
    int which = t >> 17;
    const float* S = (which==0?Sq:which==1?Sk:which==2?Sv:So) + (size_t)b*DIM*SK;
    float f0 = S[(size_t)(2*jq  )*SK + n];
    float f1 = S[(size_t)(2*jq+1)*SK + n];
    uint32_t hi, lo;
    split2(f0, f1, hi, lo);
    *(uint2*)(g_SB + (((size_t)which*BATCH + b)*64 + n)*2048 + (size_t)jq*2) =
        make_uint2(hi, lo);
}

/* =====================================================================
 * k_gemm_mma: multi-job GEMM, C = alpha * A(Mx2048) @ B^T (N=64).
 *   Double-buffered, register-prefetched. Split-pair epilogue.
 * =====================================================================*/
#define GAS 40
#define GBUF ((128 + 64) * GAS)
#define GEMM_SMEM (2 * GBUF * 4)

struct GemmJobs {
    const float*    A[7];
    const uint32_t* B[7];
    uint32_t*       C[7];
    long  sAb[7];
    long  sBb[7];
    long  sCb[7];   /* words */
    int   mtiles[7];
    float alpha[7];
};

__global__ void __launch_bounds__(256, 1) k_gemm_mma(GemmJobs J)
{
    extern __shared__ uint32_t smg[];
    int job = blockIdx.y, b = blockIdx.z;
    if ((int)blockIdx.x >= J.mtiles[job]) return;
    int tm0 = blockIdx.x * 128;
    const float*    A = J.A[job] + (size_t)b*J.sAb[job] + (size_t)tm0*DIM;
    const uint32_t* B = J.B[job] + (size_t)b*J.sBb[job];
    uint32_t*       C = J.C[job] + (size_t)b*J.sCb[job] + (size_t)tm0*SK;
    float alpha = J.alpha[job];

    int tid = threadIdx.x, lane = tid & 31, w = tid >> 5;
    int gid = lane >> 2, qd = lane & 3;
    int m0 = w*16;
    int ar = tid >> 1, ahalf = tid & 1;
    int bn = tid >> 3, bj4 = tid & 7;

    float acc[8][4] = {};
    float4 av[4];
    uint4  bv[2];

    {
        const float* Ap = A + (size_t)ar*DIM + ahalf*16;
        av[0] = ((const float4*)Ap)[0]; av[1] = ((const float4*)Ap)[1];
        av[2] = ((const float4*)Ap)[2]; av[3] = ((const float4*)Ap)[3];
        bv[0] = *(const uint4*)(B + (size_t)bn*2048 + bj4*4);
        bv[1] = *(const uint4*)(B + (size_t)(bn+32)*2048 + bj4*4);
    }
    {
        uint32_t* dA = smg;
        uint32_t* dB = smg + 128*GAS;
        #pragma unroll
        for (int i = 0; i < 4; i++) {
            uint32_t h01, l01, h23, l23;
            split2(av[i].x, av[i].y, h01, l01);
            split2(av[i].z, av[i].w, h23, l23);
            *(uint4*)(dA + (size_t)ar*GAS + ahalf*16 + i*4) =
                make_uint4(h01, l01, h23, l23);
        }
        *(uint4*)(dB + (size_t)bn*GAS + bj4*4)      = bv[0];
        *(uint4*)(dB + (size_t)(bn+32)*GAS + bj4*4) = bv[1];
    }
    __syncthreads();

    for (int it = 0; it < 64; it++) {
        uint32_t* sA = smg + (it & 1)*GBUF;
        uint32_t* sB = sA + 128*GAS;
        bool more = (it + 1 < 64);
        if (more) {
            int k0 = (it + 1)*32;
            const float* Ap = A + (size_t)ar*DIM + k0 + ahalf*16;
            av[0] = ((const float4*)Ap)[0]; av[1] = ((const float4*)Ap)[1];
            av[2] = ((const float4*)Ap)[2]; av[3] = ((const float4*)Ap)[3];
            bv[0] = *(const uint4*)(B + (size_t)bn*2048 + k0 + bj4*4);
            bv[1] = *(const uint4*)(B + (size_t)(bn+32)*2048 + k0 + bj4*4);
        }
        #pragma unroll
        for (int ks = 0; ks < 2; ks++) {
            uint2 qa0 = *(const uint2*)(sA + (size_t)(m0+gid  )*GAS + (8*ks+qd  )*2);
            uint2 qa1 = *(const uint2*)(sA + (size_t)(m0+gid+8)*GAS + (8*ks+qd  )*2);
            uint2 qa2 = *(const uint2*)(sA + (size_t)(m0+gid  )*GAS + (8*ks+qd+4)*2);
            uint2 qa3 = *(const uint2*)(sA + (size_t)(m0+gid+8)*GAS + (8*ks+qd+4)*2);
            uint32_t ah[4] = {qa0.x, qa1.x, qa2.x, qa3.x};
            uint32_t al[4] = {qa0.y, qa1.y, qa2.y, qa3.y};
            #pragma unroll
            for (int nt = 0; nt < 8; nt++) {
                uint2 kb0 = *(const uint2*)(sB + (size_t)(nt*8+gid)*GAS + (8*ks+qd  )*2);
                uint2 kb1 = *(const uint2*)(sB + (size_t)(nt*8+gid)*GAS + (8*ks+qd+4)*2);
                mma3b(acc[nt], ah, al, kb0.x, kb1.x, kb0.y, kb1.y);
            }
        }
        if (more) {
            uint32_t* dA = smg + ((it + 1) & 1)*GBUF;
            uint32_t* dB = dA + 128*GAS;
            #pragma unroll
            for (int i = 0; i < 4; i++) {
                uint32_t h01, l01, h23, l23;
                split2(av[i].x, av[i].y, h01, l01);
                split2(av[i].z, av[i].w, h23, l23);
                *(uint4*)(dA + (size_t)ar*GAS + ahalf*16 + i*4) =
                    make_uint4(h01, l01, h23, l23);
            }
            *(uint4*)(dB + (size_t)bn*GAS + bj4*4)      = bv[0];
            *(uint4*)(dB + (size_t)(bn+32)*GAS + bj4*4) = bv[1];
            __syncthreads();
        }
    }

    /* ---- epilogue: write split-pair layout ---- */
    #pragma unroll
    for (int nt = 0; nt < 8; nt++) {
        uint2 u0, u1;
        split2(acc[nt][0]*alpha, acc[nt][1]*alpha, u0.x, u0.y);
        split2(acc[nt][2]*alpha, acc[nt][3]*alpha, u1.x, u1.y);
        *(uint2*)(C + (size_t)(m0+gid  )*SK + (nt*4+qd)*2) = u0;
        *(uint2*)(C + (size_t)(m0+gid+8)*SK + (nt*4+qd)*2) = u1;
    }
}

/* =====================================================================
 * k_proj_mma: X = ASs @ Ts^T via 3-MMA bf16 split, K=64 (4 k-steps).
 *   128x64 tile, 8 warps. Inputs pre-split. Epilogues:
 *     mode 0: RoPE, *1/sqrt(HD), split -> g_qB [b,h][s][d words]
 *     mode 1: RoPE, split -> g_kB [b,kvh][s][d words]
 *     mode 2: smem transpose, split -> g_vTB [b,kvh][d][s words]
 *     mode 3: d_out fp32 [b][s][m]
 * =====================================================================*/
#define PJS 72
#define PROJ_SMEM ((128*PJS + 64*PJS) * 4)

__global__ void __launch_bounds__(256, 1) k_proj_mma(
    const float* __restrict__ freqs, float* __restrict__ dout, int phase)
{
    extern __shared__ uint32_t smp[];
    uint32_t* sA = smp;
    uint32_t* sB = smp + 128*PJS;

    int b = blockIdx.z, y = blockIdx.y;
    int mode, mt;
    if (phase)       { mode = 3; mt = y; }
    else if (y < 32) { mode = 0; mt = y; }
    else if (y < 48) { mode = 1; mt = y - 32; }
    else             { mode = 2; mt = y - 48; }
    int s0 = blockIdx.x * 128, m0g = mt * 64;

    const uint32_t* Asrc;
    const uint32_t* Bsrc;
    if      (mode == 0) { Asrc = g_ASB + ((size_t)0*BATCH + b)*SEQ*SK; Bsrc = g_TqB + (size_t)b*DIM*SK; }
    else if (mode == 1) { Asrc = g_ASB + ((size_t)1*BATCH + b)*SEQ*SK; Bsrc = g_TkB + (size_t)b*KVD*SK; }
    else if (mode == 2) { Asrc = g_ASB + ((size_t)2*BATCH + b)*SEQ*SK; Bsrc = g_TvB + (size_t)b*KVD*SK; }
    else                { Asrc = g_ASoB + (size_t)b*SEQ*SK;            Bsrc = g_ToB + (size_t)b*DIM*SK; }

    int tid = threadIdx.x, lane = tid & 31, w = tid >> 5;
    int gid = lane >> 2, qd = lane & 3;
    int m0 = w*16;

    #pragma unroll
    for (int it = 0; it < 8; it++) {
        int idx = tid + it*256;
        int r = idx >> 4, c4 = (idx & 15)*4;
        *(uint4*)(sA + (size_t)r*PJS + c4) =
            *(const uint4*)(Asrc + (size_t)(s0 + r)*SK + c4);
    }
    #pragma unroll
    for (int it = 0; it < 4; it++) {
        int idx = tid + it*256;
        int r = idx >> 4, c4 = (idx & 15)*4;
        *(uint4*)(sB + (size_t)r*PJS + c4) =
            *(const uint4*)(Bsrc + (size_t)(m0g + r)*SK + c4);
    }
    __syncthreads();

    float acc[8][4] = {};
    #pragma unroll
    for (int ks = 0; ks < 4; ks++) {
        uint2 qa0 = *(const uint2*)(sA + (size_t)(m0+gid  )*PJS + (8*ks+qd  )*2);
        uint2 qa1 = *(const uint2*)(sA + (size_t)(m0+gid+8)*PJS + (8*ks+qd  )*2);
        uint2 qa2 = *(const uint2*)(sA + (size_t)(m0+gid  )*PJS + (8*ks+qd+4)*2);
        uint2 qa3 = *(const uint2*)(sA + (size_t)(m0+gid+8)*PJS + (8*ks+qd+4)*2);
        uint32_t ah[4] = {qa0.x, qa1.x, qa2.x, qa3.x};
        uint32_t al[4] = {qa0.y, qa1.y, qa2.y, qa3.y};
        #pragma unroll
        for (int nt = 0; nt < 8; nt++) {
            uint2 kb0 = *(const uint2*)(sB + (size_t)(nt*8+gid)*PJS + (8*ks+qd  )*2);
            uint2 kb1 = *(const uint2*)(sB + (size_t)(nt*8+gid)*PJS + (8*ks+qd+4)*2);
            mma3b(acc[nt], ah, al, kb0.x, kb1.x, kb0.y, kb1.y);
        }
    }

    if (mode == 3) {
        #pragma unroll
        for (int nt = 0; nt < 8; nt++) {
            int c = nt*8 + 2*qd;
            *(float2*)(dout + ((size_t)b*SEQ + s0+m0+gid  )*DIM + m0g + c) =
                make_float2(acc[nt][0], acc[nt][1]);
            *(float2*)(dout + ((size_t)b*SEQ + s0+m0+gid+8)*DIM + m0g + c) =
                make_float2(acc[nt][2], acc[nt][3]);
        }
    } else if (mode == 2) {
        __syncthreads();
        float* st = (float*)smp;   /* [64 d][132 s] */
        #pragma unroll
        for (int nt = 0; nt < 8; nt++) {
            int c = nt*8 + 2*qd;
            st[(size_t)(c  )*132 + m0+gid  ] = acc[nt][0];
            st[(size_t)(c+1)*132 + m0+gid  ] = acc[nt][1];
            st[(size_t)(c  )*132 + m0+gid+8] = acc[nt][2];
            st[(size_t)(c+1)*132 + m0+gid+8] = acc[nt][3];
        }
        __syncthreads();
        int h = m0g >> 7, d0b = m0g & 127;
        uint32_t* Vt = g_vTB + ((size_t)(b*NKV + h)*HD + d0b)*SEQ;
        #pragma unroll
        for (int it = 0; it < 8; it++) {
            int slot = tid + it*256;
            int d = slot >> 5, s4 = (slot & 31)*4;
            float4 v = *(float4*)(st + (size_t)d*132 + s4);
            uint4 u;
            split2(v.x, v.y, u.x, u.y);
            split2(v.z, v.w, u.z, u.w);
            *(uint4*)(Vt + (size_t)d*SEQ + s0 + s4) = u;
        }
    } else {
        int h = m0g >> 7;
        uint32_t* base = (mode == 0) ? g_qB + (size_t)(b*NH  + h)*SEQ*HD
                                     : g_kB + (size_t)(b*NKV + h)*SEQ*HD;
        float sc = (mode == 0) ? INV_SQRT_HD : 1.0f;
        #pragma unroll
        for (int nt = 0; nt < 8; nt++) {
            int c  = nt*8 + 2*qd;
            int d0 = (m0g & 127) + c;
            int dh = d0 >> 1;
            int srA = s0 + m0 + gid, srB = srA + 8;
            const float* fA = freqs + ((size_t)srA*64 + dh)*2;
            float c0 = fA[0], n0 = fA[1];
            uint2 uA;
            split2((acc[nt][0]*n0 - acc[nt][1]*c0)*sc,
                   (acc[nt][0]*c0 + acc[nt][1]*n0)*sc, uA.x, uA.y);
            *(uint2*)(base + (size_t)srA*HD + d0) = uA;
            const float* fB = freqs + ((size_t)srB*64 + dh)*2;
            float c1 = fB[0], n1 = fB[1];
            uint2 uB;
            split2((acc[nt][2]*n1 - acc[nt][3]*c1)*sc,
                   (acc[nt][2]*c1 + acc[nt][3]*n1)*sc, uB.x, uB.y);
            *(uint2*)(base + (size_t)srB*HD + d0) = uB;
        }
    }
}

/* =====================================================================
 * k_flash: causal flash attention, bf16-split m16n8k16, cp.async pipe.
 *   BM=128, BN=64, 8 warps. Q/K/V pre-split in global (by proj) ->
 *   tile loads are pure cp.async 16B copies. V double-buffered; K
 *   prefetched after its last reader (post-QK barrier). No splits
 *   in-kernel except P.
 *   smem: sQ[128][136], sK[64][136], sV 2x[128][72], sP[128][72].
 * =====================================================================*/
#define QS 136
#define KS 136
#define VS 72
#define PS 72
#define SQ_OFF  0
#define SK_OFF  (128*QS)               /* 17408 */
#define SV_OFF  (SK_OFF + 64*KS)       /* 26112 */
#define VBUF    (128*VS)               /* 9216  */
#define SP_OFF  (SV_OFF + 2*VBUF)      /* 44544 */
#define FLASH_WORDS (SP_OFF + 128*PS)  /* 53760 */
#define FLASH_SMEM  (FLASH_WORDS * 4)  /* 215040 B */

__global__ void __launch_bounds__(256, 1) k_flash()
{
    extern __shared__ uint32_t smw[];
    uint32_t* sQ = smw + SQ_OFF;
    uint32_t* sK = smw + SK_OFF;
    uint32_t* sP = smw + SP_OFF;

    uint32_t smemB = (uint32_t)__cvta_generic_to_shared(smw);
    uint32_t sQa = smemB + SQ_OFF*4;
    uint32_t sKa = smemB + SK_OFF*4;
    uint32_t sVa = smemB + SV_OFF*4;

    int tid = threadIdx.x, lane = tid & 31, w = tid >> 5;
    int qt = (int)gridDim.x - 1 - (int)blockIdx.x;
    int h = blockIdx.y, b = blockIdx.z;
    int gid = lane >> 2, qd = lane & 3;

    const uint32_t* Qg = g_qB  + ((size_t)(b*NH  + h)*SEQ + (size_t)qt*128)*HD;
    const uint32_t* Kg = g_kB  + (size_t)(b*NKV + (h>>1))*SEQ*HD;
    const uint32_t* Vg = g_vTB + (size_t)(b*NKV + (h>>1))*HD*SEQ;

    /* ---- preload Q + K[0] + V[0] via cp.async ---- */
    #pragma unroll
    for (int it = 0; it < 16; it++) {
        int slot = tid + it*256;
        int r = slot >> 5, c4 = (slot & 31) * 4;
        cp16(sQa + (uint32_t)(r*QS + c4)*4, Qg + (size_t)r*HD + c4);
    }
    #pragma unroll
    for (int it = 0; it < 8; it++) {
        int slot = tid + it*256;
        int r = slot >> 5, c4 = (slot & 31) * 4;
        cp16(sKa + (uint32_t)(r*KS + c4)*4, Kg + (size_t)r*HD + c4);
    }
    #pragma unroll
    for (int it = 0; it < 8; it++) {
        int slot = tid + it*256;
        int d = slot >> 4, c4 = (slot & 15) * 4;
        cp16(sVa + (uint32_t)(d*VS + c4)*4, Vg + (size_t)d*SEQ + c4);
    }
    CP_COMMIT();
    CP_WAIT0();
    __syncthreads();

    int m0 = w*16;
    float o[16][4] = {};
    float miA = -1e30f, miB = -1e30f, liA = 0.f, liB = 0.f;
    int row_min = qt*128 + w*16;
    int row_max = row_min + 15;
    int nkt = 2*qt + 2;

    for (int kt = 0; kt < nkt; kt++) {
        uint32_t* sV = smw + SV_OFF + (kt & 1)*VBUF;
        bool active = (kt*64 <= row_max);
        bool more = (kt + 1 < nkt);

        /* ---- S = Q K^T ---- */
        float s[8][4] = {};
        if (active) {
            #pragma unroll
            for (int ks = 0; ks < 8; ks++) {
                uint2 qa0 = *(const uint2*)(sQ + (size_t)(m0+gid  )*QS + (8*ks+qd  )*2);
                uint2 qa1 = *(const uint2*)(sQ + (size_t)(m0+gid+8)*QS + (8*ks+qd  )*2);
                uint2 qa2 = *(const uint2*)(sQ + (size_t)(m0+gid  )*QS + (8*ks+qd+4)*2);
                uint2 qa3 = *(const uint2*)(sQ + (size_t)(m0+gid+8)*QS + (8*ks+qd+4)*2);
                uint32_t ah[4] = {qa0.x, qa1.x, qa2.x, qa3.x};
                uint32_t al[4] = {qa0.y, qa1.y, qa2.y, qa3.y};
                #pragma unroll
                for (int nt = 0; nt < 8; nt++) {
                    uint2 kb0 = *(const uint2*)(sK + (size_t)(nt*8+gid)*KS + (8*ks+qd  )*2);
                    uint2 kb1 = *(const uint2*)(sK + (size_t)(nt*8+gid)*KS + (8*ks+qd+4)*2);
                    mma3b(s[nt], ah, al, kb0.x, kb1.x, kb0.y, kb1.y);
                }
            }
        }
        /* all warps done reading sK -> safe to overwrite via cp.async */
        __syncthreads();
        if (more) {
            const uint32_t* Kn = Kg + (size_t)(kt+1)*64*HD;
            #pragma unroll
            for (int it = 0; it < 8; it++) {
                int slot = tid + it*256;
                int r = slot >> 5, c4 = (slot & 31) * 4;
                cp16(sKa + (uint32_t)(r*KS + c4)*4, Kn + (size_t)r*HD + c4);
            }
            uint32_t sVna = sVa + (uint32_t)(((kt+1) & 1)*VBUF)*4;
            const uint32_t* Vn = Vg + (size_t)(kt+1)*64;
            #pragma unroll
            for (int it = 0; it < 8; it++) {
                int slot = tid + it*256;
                int d = slot >> 4, c4 = (slot & 15) * 4;
                cp16(sVna + (uint32_t)(d*VS + c4)*4, Vn + (size_t)d*SEQ + c4);
            }
            CP_COMMIT();
        }

        if (active) {
            /* ---- causal mask (partial tiles only) ---- */
            if (kt*64 + 63 > row_min) {
                int rA = row_min + gid, rB = rA + 8;
                #pragma unroll
                for (int nt = 0; nt < 8; nt++) {
                    int c0 = kt*64 + nt*8 + 2*qd;
                    if (c0     > rA) s[nt][0] = -1e30f;
                    if (c0 + 1 > rA) s[nt][1] = -1e30f;
                    if (c0     > rB) s[nt][2] = -1e30f;
                    if (c0 + 1 > rB) s[nt][3] = -1e30f;
                }
            }

            /* ---- online softmax ---- */
            float mA = -1e30f, mB = -1e30f;
            #pragma unroll
            for (int nt = 0; nt < 8; nt++) {
                mA = fmaxf(mA, fmaxf(s[nt][0], s[nt][1]));
                mB = fmaxf(mB, fmaxf(s[nt][2], s[nt][3]));
            }
            mA = fmaxf(mA, __shfl_xor_sync(0xffffffffu, mA, 1));
            mA = fmaxf(mA, __shfl_xor_sync(0xffffffffu, mA, 2));
            mB = fmaxf(mB, __shfl_xor_sync(0xffffffffu, mB, 1));
            mB = fmaxf(mB, __shfl_xor_sync(0xffffffffu, mB, 2));
            float newmA = fmaxf(miA, mA), newmB = fmaxf(miB, mB);
            float alA = __expf(miA - newmA), alB = __expf(miB - newmB);
            float sumA = 0.f, sumB = 0.f;
            #pragma unroll
            for (int nt = 0; nt < 8; nt++) {
                s[nt][0] = __expf(s[nt][0] - newmA);
                s[nt][1] = __expf(s[nt][1] - newmA);
                s[nt][2] = __expf(s[nt][2] - newmB);
                s[nt][3] = __expf(s[nt][3] - newmB);
                sumA += s[nt][0] + s[nt][1];
                sumB += s[nt][2] + s[nt][3];
            }
            sumA += __shfl_xor_sync(0xffffffffu, sumA, 1);
            sumA += __shfl_xor_sync(0xffffffffu, sumA, 2);
            sumB += __shfl_xor_sync(0xffffffffu, sumB, 1);
            sumB += __shfl_xor_sync(0xffffffffu, sumB, 2);
            liA = liA*alA + sumA;  miA = newmA;
            liB = liB*alB + sumB;  miB = newmB;

            /* ---- rescale O ---- */
            #pragma unroll
            for (int nt = 0; nt < 16; nt++) {
                o[nt][0] *= alA; o[nt][1] *= alA;
                o[nt][2] *= alB; o[nt][3] *= alB;
            }

            /* ---- store P split (own warp's rows; own buffer) ---- */
            #pragma unroll
            for (int nt = 0; nt < 8; nt++) {
                uint32_t hA, lA, hB, lB;
                split2(s[nt][0], s[nt][1], hA, lA);
                split2(s[nt][2], s[nt][3], hB, lB);
                *(uint2*)(sP + (size_t)(m0+gid  )*PS + (nt*4+qd)*2) = make_uint2(hA, lA);
                *(uint2*)(sP + (size_t)(m0+gid+8)*PS + (nt*4+qd)*2) = make_uint2(hB, lB);
            }
            __syncwarp();

            /* ---- O += P V ---- */
            #pragma unroll
            for (int ks = 0; ks < 4; ks++) {
                uint2 pa0 = *(const uint2*)(sP + (size_t)(m0+gid  )*PS + (8*ks+qd  )*2);
                uint2 pa1 = *(const uint2*)(sP + (size_t)(m0+gid+8)*PS + (8*ks+qd  )*2);
                uint2 pa2 = *(const uint2*)(sP + (size_t)(m0+gid  )*PS + (8*ks+qd+4)*2);
                uint2 pa3 = *(const uint2*)(sP + (size_t)(m0+gid+8)*PS + (8*ks+qd+4)*2);
                uint32_t ph[4] = {pa0.x, pa1.x, pa2.x, pa3.x};
                uint32_t pl[4] = {pa0.y, pa1.y, pa2.y, pa3.y};
                #pragma unroll
                for (int nt = 0; nt < 16; nt++) {
                    uint2 vb0 = *(const uint2*)(sV + (size_t)(nt*8+gid)*VS + (8*ks+qd  )*2);
                    uint2 vb1 = *(const uint2*)(sV + (size_t)(nt*8+gid)*VS + (8*ks+qd+4)*2);
                    mma3b(o[nt], ph, pl, vb0.x, vb1.x, vb0.y, vb1.y);
                }
            }
        }
        if (more) CP_WAIT0();
        __syncthreads();
    }

    /* ---- epilogue: O/l -> g_ao [b, s, h*HD + d] ---- */
    float invA = 1.0f / liA, invB = 1.0f / liB;
    float* Og = g_ao + ((size_t)b*SEQ + (size_t)qt*128)*DIM + (size_t)h*HD;
    #pragma unroll
    for (int nt = 0; nt < 16; nt++) {
        int c = nt*8 + 2*qd;
        float2 vA = make_float2(o[nt][0]*invA, o[nt][1]*invA);
        float2 vB = make_float2(o[nt][2]*invB, o[nt][3]*invB);
        *(float2*)(Og + (size_t)(m0 + gid)    *DIM + c) = vA;
        *(float2*)(Og + (size_t)(m0 + gid + 8)*DIM + c) = vB;
    }
}

/* ========================= launch ========================= */
extern "C" void kernel_launch(void* const* d_in, const int* in_sizes, int n_in,
                              void* d_out, int out_size)
{
    const float* x  = (const float*)d_in[0];
    const float* wq = (const float*)d_in[1];
    const float* wk = (const float*)d_in[2];
    const float* wv = (const float*)d_in[3];
    const float* wo = (const float*)d_in[4];
    const float* Sq = (const float*)d_in[5];
    const float* Sk = (const float*)d_in[6];
    const float* Sv = (const float*)d_in[7];
    const float* So = (const float*)d_in[8];
    const float* fr = (const float*)d_in[9];
    float* out = (float*)d_out;

    cudaFuncSetAttribute(k_flash, cudaFuncAttributeMaxDynamicSharedMemorySize,
                         FLASH_SMEM);
    cudaFuncSetAttribute(k_gemm_mma, cudaFuncAttributeMaxDynamicSharedMemorySize,
                         GEMM_SMEM);
    cudaFuncSetAttribute(k_proj_mma, cudaFuncAttributeMaxDynamicSharedMemorySize,
                         PROJ_SMEM);

    uint32_t* dSB;   cudaGetSymbolAddress((void**)&dSB,   g_SB);
    uint32_t* dASB;  cudaGetSymbolAddress((void**)&dASB,  g_ASB);
    uint32_t* dASoB; cudaGetSymbolAddress((void**)&dASoB, g_ASoB);
    uint32_t* dTqB;  cudaGetSymbolAddress((void**)&dTqB,  g_TqB);
    uint32_t* dTkB;  cudaGetSymbolAddress((void**)&dTkB,  g_TkB);
    uint32_t* dTvB;  cudaGetSymbolAddress((void**)&dTvB,  g_TvB);
    uint32_t* dToB;  cudaGetSymbolAddress((void**)&dToB,  g_ToB);
    float*    dAo;   cudaGetSymbolAddress((void**)&dAo,   g_ao);

    dim3 blk(256);
    const long SBw  = 64L*2048;
    const long SBwb = (long)BATCH*SBw;

    /* pre-split sketches into MMA-B layout */
    k_splitS<<<2048, blk>>>(Sq, Sk, Sv, So);

    /* all 7 pre-attention GEMMs in ONE launch (split-pair outputs) */
    GemmJobs J = {};
    const float* As[7]  = {x, x, x, wq, wk, wv, wo};
    long sAbs[7]        = {(long)SEQ*DIM, (long)SEQ*DIM, (long)SEQ*DIM, 0, 0, 0, 0};
    int  whichB[7]      = {0, 1, 2, 0, 1, 2, 3};
    uint32_t* Cs[7]     = {dASB + 0L*BATCH*SEQ*SK, dASB + 1L*BATCH*SEQ*SK,
                           dASB + 2L*BATCH*SEQ*SK, dTqB, dTkB, dTvB, dToB};
    long sCbs[7]        = {(long)SEQ*SK, (long)SEQ*SK, (long)SEQ*SK,
                           (long)DIM*SK, (long)KVD*SK, (long)KVD*SK, (long)DIM*SK};
    int  mt[7]          = {16, 16, 16, 16, 8, 8, 16};
    float al[7]         = {1.0f/SK, 1.0f/SK, 1.0f/SK, 1.0f, 1.0f, 1.0f, 1.0f};
    for (int i = 0; i < 7; i++) {
        J.A[i] = As[i]; J.sAb[i] = sAbs[i];
        J.B[i] = dSB + (long)whichB[i]*SBwb; J.sBb[i] = SBw;
        J.C[i] = Cs[i]; J.sCb[i] = sCbs[i];
        J.mtiles[i] = mt[i]; J.alpha[i] = al[i];
    }
    k_gemm_mma<<<dim3(16, 7, BATCH), blk, GEMM_SMEM>>>(J);

    /* q/k/v projections (MMA, fused; RoPE + pre-split epilogues) */
    k_proj_mma<<<dim3(16, 64, BATCH), blk, PROJ_SMEM>>>(fr, out, 0);

    /* causal flash attention (cp.async pipelined, pre-split QKV) -> g_ao */
    k_flash<<<dim3(SEQ/128, NH, BATCH), blk, FLASH_SMEM>>>();

    /* AS_o = attn_out @ So / 64 */
    GemmJobs J2 = {};
    J2.A[0] = dAo;  J2.sAb[0] = (long)SEQ*DIM;
    J2.B[0] = dSB + 3L*SBwb; J2.sBb[0] = SBw;
    J2.C[0] = dASoB; J2.sCb[0] = (long)SEQ*SK;
    J2.mtiles[0] = 16; J2.alpha[0] = 1.0f/SK;
    k_gemm_mma<<<dim3(16, 1, BATCH), blk, GEMM_SMEM>>>(J2);

    /* final = AS_o @ To^T -> d_out */
    k_proj_mma<<<dim3(16, 32, BATCH), blk, PROJ_SMEM>>>(fr, out, 1);
}